// round 13
// baseline (speedup 1.0000x reference)
#include <cuda_runtime.h>
#include <cuda_bf16.h>
#include <math.h>
#include <stdint.h>

// Problem constants
#define BB   2
#define SS   4096
#define DD   512
#define HH   8
#define HD   64
#define HALFW 256
#define MROWS (BB*SS)   // 8192

// ---------------------------------------------------------------------------
// Scratch (static device globals: allocation-free)
// ---------------------------------------------------------------------------
__device__ float g_attn[BB*SS*DD];
__device__ float g_y[BB*SS*DD];
__device__ __nv_bfloat16 g_wHiT[4*DD*DD];   // [n][k] transposed, 4 matrices
__device__ __nv_bfloat16 g_wLoT[4*DD*DD];
__device__ __nv_bfloat16 g_qHi[MROWS*DD], g_qLo[MROWS*DD];
__device__ __nv_bfloat16 g_kHi[MROWS*DD], g_kLo[MROWS*DD];
__device__ __nv_bfloat16 g_vHi[MROWS*DD], g_vLo[MROWS*DD];

// ---------------------------------------------------------------------------
// mma.sync / ldmatrix helpers (sm_80+ PTX — assembles at plain sm_103)
// ---------------------------------------------------------------------------
__device__ __forceinline__ uint32_t smem_u32(const void* p) {
    uint32_t a;
    asm("{ .reg .u64 t; cvta.to.shared.u64 t, %1; cvt.u32.u64 %0, t; }"
        : "=r"(a) : "l"(p));
    return a;
}
__device__ __forceinline__ void ldm4(uint32_t* r, uint32_t a) {
    asm volatile("ldmatrix.sync.aligned.m8n8.x4.shared.b16 {%0,%1,%2,%3}, [%4];"
                 : "=r"(r[0]), "=r"(r[1]), "=r"(r[2]), "=r"(r[3]) : "r"(a));
}
__device__ __forceinline__ void ldm4t(uint32_t* r, uint32_t a) {
    asm volatile("ldmatrix.sync.aligned.m8n8.x4.trans.shared.b16 {%0,%1,%2,%3}, [%4];"
                 : "=r"(r[0]), "=r"(r[1]), "=r"(r[2]), "=r"(r[3]) : "r"(a));
}
__device__ __forceinline__ void ldm2(uint32_t* r, uint32_t a) {
    asm volatile("ldmatrix.sync.aligned.m8n8.x2.shared.b16 {%0,%1}, [%2];"
                 : "=r"(r[0]), "=r"(r[1]) : "r"(a));
}
__device__ __forceinline__ void mma16816(float* c, const uint32_t* a, const uint32_t* b) {
    asm volatile("mma.sync.aligned.m16n8k16.row.col.f32.bf16.bf16.f32 "
                 "{%0,%1,%2,%3}, {%4,%5,%6,%7}, {%8,%9}, {%0,%1,%2,%3};"
                 : "+f"(c[0]), "+f"(c[1]), "+f"(c[2]), "+f"(c[3])
                 : "r"(a[0]), "r"(a[1]), "r"(a[2]), "r"(a[3]),
                   "r"(b[0]), "r"(b[1]));
}
__device__ __forceinline__ void cpa16(uint32_t s, const void* g) {
    asm volatile("cp.async.cg.shared.global [%0], [%1], 16;" :: "r"(s), "l"(g));
}
__device__ __forceinline__ uint32_t pkbf(__nv_bfloat16 a, __nv_bfloat16 b) {
    __nv_bfloat162 t = __halves2bfloat162(a, b);
    return *(uint32_t*)&t;
}

// ---------------------------------------------------------------------------
// Weight conversion (batched): W[512][512] fp32 -> WT_hi/lo [n][k] bf16
// ---------------------------------------------------------------------------
__global__ void convW4(const float* __restrict__ W0, const float* __restrict__ W1,
                       const float* __restrict__ W2, const float* __restrict__ W3)
{
    const float* W = (blockIdx.z == 0) ? W0 : (blockIdx.z == 1) ? W1
                   : (blockIdx.z == 2) ? W2 : W3;
    __nv_bfloat16* hiT = g_wHiT + (size_t)blockIdx.z * DD * DD;
    __nv_bfloat16* loT = g_wLoT + (size_t)blockIdx.z * DD * DD;
    __shared__ float ts[32][33];
    int n0 = blockIdx.x * 32, k0 = blockIdx.y * 32;
    int tx = threadIdx.x, ty = threadIdx.y;
    ts[ty][tx] = W[(size_t)(k0 + ty) * DD + n0 + tx];
    __syncthreads();
    float w = ts[tx][ty];                 // = W[k0+tx][n0+ty]
    __nv_bfloat16 h = __float2bfloat16(w);
    float rlo = w - __bfloat162float(h);
    hiT[(size_t)(n0 + ty) * DD + k0 + tx] = h;
    loT[(size_t)(n0 + ty) * DD + k0 + tx] = __float2bfloat16(rlo);
}

// ---------------------------------------------------------------------------
// Tensor-core GEMM: out = A[M,K] @ W[K,N] + bias  (bf16 split, 3-pass).
// A fp32 converted in-kernel; W pre-transposed hi/lo. CTA 128x128, KC=32.
// Output either fp32 (Cf) or bf16 split (Chi/Clo) scaled by `scale`.
// ---------------------------------------------------------------------------
#define MT 128
#define NT 128
#define KC 32
#define TSTRIDE 80
#define TILE_B (128 * TSTRIDE)
#define BUF_B  (4 * TILE_B)
#define GEMM_SMEM (2 * BUF_B)             // 81920 bytes

__device__ __forceinline__ void ldg_tiles(const float* __restrict__ A,
                                          const __nv_bfloat16* __restrict__ Bh,
                                          const __nv_bfloat16* __restrict__ Bl,
                                          int m0, int n0, int kc, int tid,
                                          uint4* pa, uint4* pbh, uint4* pbl)
{
    #pragma unroll
    for (int i = 0; i < 4; i++) {
        int q = tid + 256 * i;
        int r = q >> 3, c4 = (q & 7) << 2;
        pa[i] = *(const uint4*)(A + (size_t)(m0 + r) * DD + kc + c4);
    }
    #pragma unroll
    for (int i = 0; i < 2; i++) {
        int q = tid + 256 * i;
        int r = q >> 2, c8 = (q & 3) << 3;
        size_t g = (size_t)(n0 + r) * DD + kc + c8;
        pbh[i] = *(const uint4*)(Bh + g);
        pbl[i] = *(const uint4*)(Bl + g);
    }
}

__device__ __forceinline__ void sts_tiles(char* buf, int tid,
                                          const uint4* pa, const uint4* pbh, const uint4* pbl)
{
    #pragma unroll
    for (int i = 0; i < 4; i++) {
        int q = tid + 256 * i;
        int r = q >> 3, cb = (q & 7) * 8;
        float4 v = *(const float4*)&pa[i];
        __nv_bfloat16 h0 = __float2bfloat16(v.x);
        __nv_bfloat16 h1 = __float2bfloat16(v.y);
        __nv_bfloat16 h2 = __float2bfloat16(v.z);
        __nv_bfloat16 h3 = __float2bfloat16(v.w);
        uint2 hu; hu.x = pkbf(h0, h1); hu.y = pkbf(h2, h3);
        uint2 lu;
        lu.x = pkbf(__float2bfloat16(v.x - __bfloat162float(h0)),
                    __float2bfloat16(v.y - __bfloat162float(h1)));
        lu.y = pkbf(__float2bfloat16(v.z - __bfloat162float(h2)),
                    __float2bfloat16(v.w - __bfloat162float(h3)));
        *(uint2*)(buf + 0 * TILE_B + r * TSTRIDE + cb) = hu;
        *(uint2*)(buf + 1 * TILE_B + r * TSTRIDE + cb) = lu;
    }
    #pragma unroll
    for (int i = 0; i < 2; i++) {
        int q = tid + 256 * i;
        int r = q >> 2, cb = (q & 3) * 16;
        *(uint4*)(buf + 2 * TILE_B + r * TSTRIDE + cb) = pbh[i];
        *(uint4*)(buf + 3 * TILE_B + r * TSTRIDE + cb) = pbl[i];
    }
}

__global__ void __launch_bounds__(256, 1)
tc_gemm(const float* __restrict__ A,
        const __nv_bfloat16* __restrict__ bHiT, const __nv_bfloat16* __restrict__ bLoT,
        const float* __restrict__ bias,
        float* __restrict__ Cf,
        __nv_bfloat16* __restrict__ Chi, __nv_bfloat16* __restrict__ Clo,
        float scale)
{
    extern __shared__ char sm[];
    const int tid = threadIdx.x;
    const int wid = tid >> 5, lane = tid & 31;
    const int wm = wid & 1, wn = wid >> 1;
    const int m0 = blockIdx.x * MT;
    const int n0 = blockIdx.y * NT;

    float acc[4][4][4];
    #pragma unroll
    for (int i = 0; i < 4; i++)
        #pragma unroll
        for (int j = 0; j < 4; j++)
            #pragma unroll
            for (int e = 0; e < 4; e++) acc[i][j][e] = 0.f;

    uint4 pa[4], pbh[2], pbl[2];
    ldg_tiles(A, bHiT, bLoT, m0, n0, 0, tid, pa, pbh, pbl);
    sts_tiles(sm, tid, pa, pbh, pbl);
    __syncthreads();

    const int aRow  = wm * 64 + (lane & 15);
    const int aKoff = ((lane >> 4) & 1) * 16;
    const int bRow  = wn * 32 + (lane & 7);
    const int bKoff = ((lane >> 3) & 1) * 16;

    for (int c = 0; c < 16; c++) {
        char* buf = sm + (c & 1) * BUF_B;
        if (c < 15)
            ldg_tiles(A, bHiT, bLoT, m0, n0, (c + 1) * KC, tid, pa, pbh, pbl);

        const uint32_t base = smem_u32(buf);
        #pragma unroll
        for (int ks = 0; ks < 2; ks++) {
            uint32_t bh[4][2], bl[4][2];
            #pragma unroll
            for (int nt = 0; nt < 4; nt++) {
                uint32_t ad = base + 2 * TILE_B + (bRow + nt * 8) * TSTRIDE
                            + ks * 32 + bKoff;
                ldm2(bh[nt], ad);
                ldm2(bl[nt], ad + TILE_B);
            }
            #pragma unroll
            for (int mt = 0; mt < 4; mt++) {
                uint32_t ah[4], al[4];
                uint32_t ad = base + (aRow + mt * 16) * TSTRIDE + ks * 32 + aKoff;
                ldm4(ah, ad);
                ldm4(al, ad + TILE_B);
                #pragma unroll
                for (int nt = 0; nt < 4; nt++) {
                    mma16816(acc[mt][nt], ah, bh[nt]);
                    mma16816(acc[mt][nt], ah, bl[nt]);
                    mma16816(acc[mt][nt], al, bh[nt]);
                }
            }
        }
        if (c < 15)
            sts_tiles(sm + ((c + 1) & 1) * BUF_B, tid, pa, pbh, pbl);
        __syncthreads();
    }

    const int mBase = m0 + wm * 64 + (lane >> 2);
    const int nBase = n0 + wn * 32 + (lane & 3) * 2;
    if (Cf) {
        #pragma unroll
        for (int nt = 0; nt < 4; nt++) {
            int gn = nBase + nt * 8;
            float b0 = bias[gn], b1 = bias[gn + 1];
            #pragma unroll
            for (int mt = 0; mt < 4; mt++) {
                int gm = mBase + mt * 16;
                *(float2*)&Cf[(size_t)gm * DD + gn] =
                    make_float2(acc[mt][nt][0] + b0, acc[mt][nt][1] + b1);
                *(float2*)&Cf[(size_t)(gm + 8) * DD + gn] =
                    make_float2(acc[mt][nt][2] + b0, acc[mt][nt][3] + b1);
            }
        }
    } else {
        #pragma unroll
        for (int nt = 0; nt < 4; nt++) {
            int gn = nBase + nt * 8;
            float b0 = bias[gn], b1 = bias[gn + 1];
            #pragma unroll
            for (int mt = 0; mt < 4; mt++) {
                int gm = mBase + mt * 16;
                #pragma unroll
                for (int rr = 0; rr < 2; rr++) {
                    float v0 = (acc[mt][nt][rr * 2 + 0] + b0) * scale;
                    float v1 = (acc[mt][nt][rr * 2 + 1] + b1) * scale;
                    __nv_bfloat16 h0 = __float2bfloat16(v0);
                    __nv_bfloat16 h1 = __float2bfloat16(v1);
                    size_t off = (size_t)(gm + rr * 8) * DD + gn;
                    *(uint32_t*)&Chi[off] = pkbf(h0, h1);
                    *(uint32_t*)&Clo[off] = pkbf(
                        __float2bfloat16(v0 - __bfloat162float(h0)),
                        __float2bfloat16(v1 - __bfloat162float(h1)));
                }
            }
        }
    }
}

// ---------------------------------------------------------------------------
// Tensor-core sliding-window flash attention.
// Grid (S/64, H, B), 128 threads (4 warps x 16 query rows).
// Q pre-scaled bf16 hi/lo from GEMM epilogue. K non-trans ldmatrix,
// V trans ldmatrix, P split in-register. 3-pass bf16 everywhere.
// All processed key tiles are fully in [0,S) (64-aligned band) -> band mask only.
// ---------------------------------------------------------------------------
#define AT_STRIDE 144
#define PLANE (64 * AT_STRIDE)            // 9216
#define KV_OFF (2 * PLANE)                // Q hi/lo first
#define KV_BUF (4 * PLANE)                // Khi,Klo,Vhi,Vlo
#define ATTN_SMEM (KV_OFF + 2 * KV_BUF)   // 92160 bytes

__device__ __forceinline__ void stage_kv(uint32_t sbase, size_t rowb, int h,
                                         int n0, int tid)
{
    const int c = (tid & 7) * 16;
    #pragma unroll
    for (int i = 0; i < 16; i++) {
        const __nv_bfloat16* src = (i < 4) ? g_kHi : (i < 8) ? g_kLo
                                 : (i < 12) ? g_vHi : g_vLo;
        int rr = (tid + 128 * (i & 3)) >> 3;
        const char* g = (const char*)(src + (rowb + n0 + rr) * DD + h * HD) + c;
        cpa16(sbase + (i >> 2) * PLANE + rr * AT_STRIDE + c, g);
    }
}

__global__ void __launch_bounds__(128, 2) attn_tc()
{
    extern __shared__ char smc[];
    const uint32_t smb = smem_u32(smc);
    const int tid = threadIdx.x, wid = tid >> 5, lane = tid & 31;
    const int b = blockIdx.z, h = blockIdx.y, m0 = blockIdx.x * 64;
    const size_t rowb = (size_t)b * SS;
    const int wq = wid * 16;

    // stage Q hi/lo (group 0, together with first KV tile)
    {
        const int c = (tid & 7) * 16;
        #pragma unroll
        for (int i = 0; i < 8; i++) {
            const __nv_bfloat16* src = (i < 4) ? g_qHi : g_qLo;
            int rr = (tid + 128 * (i & 3)) >> 3;
            const char* g = (const char*)(src + (rowb + m0 + rr) * DD + h * HD) + c;
            cpa16(smb + (i >> 2) * PLANE + rr * AT_STRIDE + c, g);
        }
    }
    int t_lo = (m0 >= 256) ? 0 : (256 - m0) / 64;
    int t_hi = (SS - 64 - m0 + 256) / 64; if (t_hi > 8) t_hi = 8;

    stage_kv(smb + KV_OFF, rowb, h, m0 - 256 + t_lo * 64, tid);
    asm volatile("cp.async.commit_group;" ::: "memory");

    uint32_t qh[4][4], ql[4][4];
    float O[8][4];
    #pragma unroll
    for (int i = 0; i < 8; i++)
        #pragma unroll
        for (int e = 0; e < 4; e++) O[i][e] = 0.f;
    float mi0 = -1e30f, mi1 = -1e30f, li0 = 0.f, li1 = 0.f;

    for (int t = t_lo; t <= t_hi; t++) {
        const uint32_t cbase = smb + KV_OFF + ((t - t_lo) & 1) * KV_BUF;
        if (t < t_hi) {
            stage_kv(smb + KV_OFF + ((t - t_lo + 1) & 1) * KV_BUF,
                     rowb, h, m0 - 256 + (t + 1) * 64, tid);
            asm volatile("cp.async.commit_group;" ::: "memory");
            asm volatile("cp.async.wait_group 1;" ::: "memory");
        } else {
            asm volatile("cp.async.wait_group 0;" ::: "memory");
        }
        __syncthreads();

        if (t == t_lo) {
            #pragma unroll
            for (int ks = 0; ks < 4; ks++) {
                uint32_t a = smb + (wq + (lane & 15)) * AT_STRIDE
                           + ks * 32 + ((lane >> 4) & 1) * 16;
                ldm4(qh[ks], a);
                ldm4(ql[ks], a + PLANE);
            }
        }
        const int n0 = m0 - 256 + t * 64;

        // ---- S = Q K^T (16 x 64 per warp) ----
        float s[8][4];
        #pragma unroll
        for (int nt = 0; nt < 8; nt++) {
            uint32_t kh[8], kl[8];
            #pragma unroll
            for (int kp = 0; kp < 2; kp++) {
                uint32_t a = cbase + (nt * 8 + (lane & 7)) * AT_STRIDE
                           + kp * 64 + (lane >> 3) * 16;
                ldm4(&kh[kp * 4], a);
                ldm4(&kl[kp * 4], a + PLANE);
            }
            #pragma unroll
            for (int e = 0; e < 4; e++) s[nt][e] = 0.f;
            #pragma unroll
            for (int ks = 0; ks < 4; ks++) {
                mma16816(s[nt], qh[ks], &kh[ks * 2]);
                mma16816(s[nt], qh[ks], &kl[ks * 2]);
                mma16816(s[nt], ql[ks], &kh[ks * 2]);
            }
        }

        // ---- band mask + online softmax ----
        const int colb = n0 + (lane & 3) * 2;
        const int row0 = m0 + wq + (lane >> 2);
        #pragma unroll
        for (int nt = 0; nt < 8; nt++) {
            int kg = colb + nt * 8;
            if (abs(kg     - row0)     > HALFW) s[nt][0] = -1e30f;
            if (abs(kg + 1 - row0)     > HALFW) s[nt][1] = -1e30f;
            if (abs(kg     - row0 - 8) > HALFW) s[nt][2] = -1e30f;
            if (abs(kg + 1 - row0 - 8) > HALFW) s[nt][3] = -1e30f;
        }
        float mx0 = -1e30f, mx1 = -1e30f;
        #pragma unroll
        for (int nt = 0; nt < 8; nt++) {
            mx0 = fmaxf(mx0, fmaxf(s[nt][0], s[nt][1]));
            mx1 = fmaxf(mx1, fmaxf(s[nt][2], s[nt][3]));
        }
        mx0 = fmaxf(mx0, __shfl_xor_sync(0xffffffffu, mx0, 1));
        mx0 = fmaxf(mx0, __shfl_xor_sync(0xffffffffu, mx0, 2));
        mx1 = fmaxf(mx1, __shfl_xor_sync(0xffffffffu, mx1, 1));
        mx1 = fmaxf(mx1, __shfl_xor_sync(0xffffffffu, mx1, 2));
        float mn0 = fmaxf(mi0, mx0), mn1 = fmaxf(mi1, mx1);
        float cr0 = __expf(mi0 - mn0), cr1 = __expf(mi1 - mn1);
        mi0 = mn0; mi1 = mn1;
        float rs0 = 0.f, rs1 = 0.f;
        #pragma unroll
        for (int nt = 0; nt < 8; nt++) {
            s[nt][0] = __expf(s[nt][0] - mn0); rs0 += s[nt][0];
            s[nt][1] = __expf(s[nt][1] - mn0); rs0 += s[nt][1];
            s[nt][2] = __expf(s[nt][2] - mn1); rs1 += s[nt][2];
            s[nt][3] = __expf(s[nt][3] - mn1); rs1 += s[nt][3];
        }
        rs0 += __shfl_xor_sync(0xffffffffu, rs0, 1);
        rs0 += __shfl_xor_sync(0xffffffffu, rs0, 2);
        rs1 += __shfl_xor_sync(0xffffffffu, rs1, 1);
        rs1 += __shfl_xor_sync(0xffffffffu, rs1, 2);
        li0 = li0 * cr0 + rs0;
        li1 = li1 * cr1 + rs1;
        #pragma unroll
        for (int nt = 0; nt < 8; nt++) {
            O[nt][0] *= cr0; O[nt][1] *= cr0;
            O[nt][2] *= cr1; O[nt][3] *= cr1;
        }

        // ---- O += P V (P split hi/lo from accum fragments) ----
        #pragma unroll
        for (int ks = 0; ks < 4; ks++) {
            uint32_t aph[4], apl[4];
            #pragma unroll
            for (int j = 0; j < 4; j++) {
                int nt = ks * 2 + (j >> 1);
                int eb = (j & 1) * 2;
                float x0 = s[nt][eb], x1 = s[nt][eb + 1];
                __nv_bfloat16 h0 = __float2bfloat16(x0);
                __nv_bfloat16 h1 = __float2bfloat16(x1);
                aph[j] = pkbf(h0, h1);
                apl[j] = pkbf(__float2bfloat16(x0 - __bfloat162float(h0)),
                              __float2bfloat16(x1 - __bfloat162float(h1)));
            }
            #pragma unroll
            for (int dp = 0; dp < 4; dp++) {
                uint32_t vh[4], vl[4];
                uint32_t a = cbase + 2 * PLANE + (ks * 16 + (lane & 15)) * AT_STRIDE
                           + dp * 32 + ((lane >> 4) & 1) * 16;
                ldm4t(vh, a);
                ldm4t(vl, a + PLANE);
                mma16816(O[2 * dp],     aph, &vh[0]);
                mma16816(O[2 * dp],     aph, &vl[0]);
                mma16816(O[2 * dp],     apl, &vh[0]);
                mma16816(O[2 * dp + 1], aph, &vh[2]);
                mma16816(O[2 * dp + 1], aph, &vl[2]);
                mma16816(O[2 * dp + 1], apl, &vh[2]);
            }
        }
        __syncthreads();
    }

    // ---- normalize + store fp32 ----
    float iv0 = 1.f / li0, iv1 = 1.f / li1;
    const int row0 = m0 + wq + (lane >> 2);
    #pragma unroll
    for (int nt = 0; nt < 8; nt++) {
        int col = h * HD + nt * 8 + (lane & 3) * 2;
        *(float2*)&g_attn[(rowb + row0) * DD + col] =
            make_float2(O[nt][0] * iv0, O[nt][1] * iv0);
        *(float2*)&g_attn[(rowb + row0 + 8) * DD + col] =
            make_float2(O[nt][2] * iv1, O[nt][3] * iv1);
    }
}

// ----------------------------------------------------------------------------
// out = LayerNorm(val + y) * gamma + beta.   One block (256 thr) per row.
// ----------------------------------------------------------------------------
__global__ void add_ln(const float* __restrict__ val, const float* __restrict__ y,
                       const float* __restrict__ gamma, const float* __restrict__ beta,
                       float* __restrict__ out)
{
    const int row = blockIdx.x;
    const int t = threadIdx.x;
    const size_t base = (size_t)row * DD;

    float v0 = val[base + t]       + y[base + t];
    float v1 = val[base + t + 256] + y[base + t + 256];
    float s  = v0 + v1;
    float sq = v0 * v0 + v1 * v1;

    #pragma unroll
    for (int m = 16; m >= 1; m >>= 1) {
        s  += __shfl_xor_sync(0xffffffffu, s,  m);
        sq += __shfl_xor_sync(0xffffffffu, sq, m);
    }
    __shared__ float ssum[8], ssq[8];
    int w = t >> 5, lane = t & 31;
    if (lane == 0) { ssum[w] = s; ssq[w] = sq; }
    __syncthreads();
    float S = 0.f, SQ = 0.f;
    #pragma unroll
    for (int i = 0; i < 8; i++) { S += ssum[i]; SQ += ssq[i]; }

    float mu  = S * (1.0f / DD);
    float var = SQ * (1.0f / DD) - mu * mu;
    float inv = rsqrtf(var + 1e-5f);

    out[base + t]       = (v0 - mu) * inv * gamma[t]       + beta[t];
    out[base + t + 256] = (v1 - mu) * inv * gamma[t + 256] + beta[t + 256];
}

// ----------------------------------------------------------------------------
extern "C" void kernel_launch(void* const* d_in, const int* in_sizes, int n_in,
                              void* d_out, int out_size)
{
    const float* val   = (const float*)d_in[0];
    const float* Wq    = (const float*)d_in[1];
    const float* bq    = (const float*)d_in[2];
    const float* Wk    = (const float*)d_in[3];
    const float* bk    = (const float*)d_in[4];
    const float* Wv    = (const float*)d_in[5];
    const float* bv    = (const float*)d_in[6];
    const float* Wo    = (const float*)d_in[7];
    const float* bo    = (const float*)d_in[8];
    const float* gamma = (const float*)d_in[9];
    const float* beta  = (const float*)d_in[10];
    float* out = (float*)d_out;

    float *pa, *py;
    __nv_bfloat16 *wHiT, *wLoT, *qHi, *qLo, *kHi, *kLo, *vHi, *vLo;
    cudaGetSymbolAddress((void**)&pa, g_attn);
    cudaGetSymbolAddress((void**)&py, g_y);
    cudaGetSymbolAddress((void**)&wHiT, g_wHiT);
    cudaGetSymbolAddress((void**)&wLoT, g_wLoT);
    cudaGetSymbolAddress((void**)&qHi, g_qHi);
    cudaGetSymbolAddress((void**)&qLo, g_qLo);
    cudaGetSymbolAddress((void**)&kHi, g_kHi);
    cudaGetSymbolAddress((void**)&kLo, g_kLo);
    cudaGetSymbolAddress((void**)&vHi, g_vHi);
    cudaGetSymbolAddress((void**)&vLo, g_vLo);

    cudaFuncSetAttribute(tc_gemm,
                         cudaFuncAttributeMaxDynamicSharedMemorySize, GEMM_SMEM);
    cudaFuncSetAttribute(attn_tc,
                         cudaFuncAttributeMaxDynamicSharedMemorySize, ATTN_SMEM);

    convW4<<<dim3(16, 16, 4), dim3(32, 32)>>>(Wq, Wk, Wv, Wo);

    dim3 ggemm(MROWS / MT, DD / NT);   // (64, 4)
    // QKV projections: bf16 split outputs (Q pre-scaled by 1/sqrt(HD)=0.125)
    tc_gemm<<<ggemm, 256, GEMM_SMEM>>>(val, wHiT + 0 * DD * DD, wLoT + 0 * DD * DD,
                                       bq, nullptr, qHi, qLo, 0.125f);
    tc_gemm<<<ggemm, 256, GEMM_SMEM>>>(val, wHiT + 1 * DD * DD, wLoT + 1 * DD * DD,
                                       bk, nullptr, kHi, kLo, 1.0f);
    tc_gemm<<<ggemm, 256, GEMM_SMEM>>>(val, wHiT + 2 * DD * DD, wLoT + 2 * DD * DD,
                                       bv, nullptr, vHi, vLo, 1.0f);

    dim3 gattn(SS / 64, HH, BB);       // (64, 8, 2)
    attn_tc<<<gattn, 128, ATTN_SMEM>>>();

    // O projection: fp32 output
    tc_gemm<<<ggemm, 256, GEMM_SMEM>>>(pa, wHiT + 3 * DD * DD, wLoT + 3 * DD * DD,
                                       bo, py, nullptr, nullptr, 1.0f);

    add_ln<<<MROWS, 256>>>(val, py, gamma, beta, out);
}

// round 14
// speedup vs baseline: 1.0068x; 1.0068x over previous
#include <cuda_runtime.h>
#include <cuda_bf16.h>
#include <math.h>
#include <stdint.h>

// Problem constants
#define BB   2
#define SS   4096
#define DD   512
#define HH   8
#define HD   64
#define HALFW 256
#define MROWS (BB*SS)   // 8192

// ---------------------------------------------------------------------------
// Scratch (static device globals: allocation-free)
// ---------------------------------------------------------------------------
__device__ float g_attn[BB*SS*DD];
__device__ float g_y[BB*SS*DD];
__device__ __nv_bfloat16 g_wHiT[4*DD*DD];   // [n][k] transposed, 4 matrices
__device__ __nv_bfloat16 g_wLoT[4*DD*DD];
__device__ __nv_bfloat16 g_qHi[MROWS*DD], g_qLo[MROWS*DD];
__device__ __nv_bfloat16 g_kHi[MROWS*DD], g_kLo[MROWS*DD];
__device__ __nv_bfloat16 g_vHi[MROWS*DD], g_vLo[MROWS*DD];

// ---------------------------------------------------------------------------
// mma.sync / ldmatrix helpers (sm_80+ PTX — assembles at plain sm_103)
// ---------------------------------------------------------------------------
__device__ __forceinline__ uint32_t smem_u32(const void* p) {
    uint32_t a;
    asm("{ .reg .u64 t; cvta.to.shared.u64 t, %1; cvt.u32.u64 %0, t; }"
        : "=r"(a) : "l"(p));
    return a;
}
__device__ __forceinline__ void ldm4(uint32_t* r, uint32_t a) {
    asm volatile("ldmatrix.sync.aligned.m8n8.x4.shared.b16 {%0,%1,%2,%3}, [%4];"
                 : "=r"(r[0]), "=r"(r[1]), "=r"(r[2]), "=r"(r[3]) : "r"(a));
}
__device__ __forceinline__ void ldm4t(uint32_t* r, uint32_t a) {
    asm volatile("ldmatrix.sync.aligned.m8n8.x4.trans.shared.b16 {%0,%1,%2,%3}, [%4];"
                 : "=r"(r[0]), "=r"(r[1]), "=r"(r[2]), "=r"(r[3]) : "r"(a));
}
__device__ __forceinline__ void ldm2(uint32_t* r, uint32_t a) {
    asm volatile("ldmatrix.sync.aligned.m8n8.x2.shared.b16 {%0,%1}, [%2];"
                 : "=r"(r[0]), "=r"(r[1]) : "r"(a));
}
__device__ __forceinline__ void mma16816(float* c, const uint32_t* a, const uint32_t* b) {
    asm volatile("mma.sync.aligned.m16n8k16.row.col.f32.bf16.bf16.f32 "
                 "{%0,%1,%2,%3}, {%4,%5,%6,%7}, {%8,%9}, {%0,%1,%2,%3};"
                 : "+f"(c[0]), "+f"(c[1]), "+f"(c[2]), "+f"(c[3])
                 : "r"(a[0]), "r"(a[1]), "r"(a[2]), "r"(a[3]),
                   "r"(b[0]), "r"(b[1]));
}
__device__ __forceinline__ void cpa16(uint32_t s, const void* g) {
    asm volatile("cp.async.cg.shared.global [%0], [%1], 16;" :: "r"(s), "l"(g));
}
__device__ __forceinline__ uint32_t pkbf(__nv_bfloat16 a, __nv_bfloat16 b) {
    __nv_bfloat162 t = __halves2bfloat162(a, b);
    return *(uint32_t*)&t;
}

// ---------------------------------------------------------------------------
// Weight conversion (batched): W[512][512] fp32 -> WT_hi/lo [n][k] bf16
// ---------------------------------------------------------------------------
__global__ void convW4(const float* __restrict__ W0, const float* __restrict__ W1,
                       const float* __restrict__ W2, const float* __restrict__ W3)
{
    const float* W = (blockIdx.z == 0) ? W0 : (blockIdx.z == 1) ? W1
                   : (blockIdx.z == 2) ? W2 : W3;
    __nv_bfloat16* hiT = g_wHiT + (size_t)blockIdx.z * DD * DD;
    __nv_bfloat16* loT = g_wLoT + (size_t)blockIdx.z * DD * DD;
    __shared__ float ts[32][33];
    int n0 = blockIdx.x * 32, k0 = blockIdx.y * 32;
    int tx = threadIdx.x, ty = threadIdx.y;
    ts[ty][tx] = W[(size_t)(k0 + ty) * DD + n0 + tx];
    __syncthreads();
    float w = ts[tx][ty];                 // = W[k0+tx][n0+ty]
    __nv_bfloat16 h = __float2bfloat16(w);
    float rlo = w - __bfloat162float(h);
    hiT[(size_t)(n0 + ty) * DD + k0 + tx] = h;
    loT[(size_t)(n0 + ty) * DD + k0 + tx] = __float2bfloat16(rlo);
}

// ---------------------------------------------------------------------------
// Tensor-core GEMM: out = A[M,K] @ W[K,N] + bias  (bf16 split, 3-pass).
// A fp32 converted in-kernel; W pre-transposed hi/lo. CTA 128x128, KC=32.
// Output either fp32 (Cf) or bf16 split (Chi/Clo) scaled by `scale`.
// ---------------------------------------------------------------------------
#define MT 128
#define NT 128
#define KC 32
#define TSTRIDE 80
#define TILE_B (128 * TSTRIDE)
#define BUF_B  (4 * TILE_B)
#define GEMM_SMEM (2 * BUF_B)             // 81920 bytes

__device__ __forceinline__ void ldg_tiles(const float* __restrict__ A,
                                          const __nv_bfloat16* __restrict__ Bh,
                                          const __nv_bfloat16* __restrict__ Bl,
                                          int m0, int n0, int kc, int tid,
                                          uint4* pa, uint4* pbh, uint4* pbl)
{
    #pragma unroll
    for (int i = 0; i < 4; i++) {
        int q = tid + 256 * i;
        int r = q >> 3, c4 = (q & 7) << 2;
        pa[i] = *(const uint4*)(A + (size_t)(m0 + r) * DD + kc + c4);
    }
    #pragma unroll
    for (int i = 0; i < 2; i++) {
        int q = tid + 256 * i;
        int r = q >> 2, c8 = (q & 3) << 3;
        size_t g = (size_t)(n0 + r) * DD + kc + c8;
        pbh[i] = *(const uint4*)(Bh + g);
        pbl[i] = *(const uint4*)(Bl + g);
    }
}

__device__ __forceinline__ void sts_tiles(char* buf, int tid,
                                          const uint4* pa, const uint4* pbh, const uint4* pbl)
{
    #pragma unroll
    for (int i = 0; i < 4; i++) {
        int q = tid + 256 * i;
        int r = q >> 3, cb = (q & 7) * 8;
        float4 v = *(const float4*)&pa[i];
        __nv_bfloat16 h0 = __float2bfloat16(v.x);
        __nv_bfloat16 h1 = __float2bfloat16(v.y);
        __nv_bfloat16 h2 = __float2bfloat16(v.z);
        __nv_bfloat16 h3 = __float2bfloat16(v.w);
        uint2 hu; hu.x = pkbf(h0, h1); hu.y = pkbf(h2, h3);
        uint2 lu;
        lu.x = pkbf(__float2bfloat16(v.x - __bfloat162float(h0)),
                    __float2bfloat16(v.y - __bfloat162float(h1)));
        lu.y = pkbf(__float2bfloat16(v.z - __bfloat162float(h2)),
                    __float2bfloat16(v.w - __bfloat162float(h3)));
        *(uint2*)(buf + 0 * TILE_B + r * TSTRIDE + cb) = hu;
        *(uint2*)(buf + 1 * TILE_B + r * TSTRIDE + cb) = lu;
    }
    #pragma unroll
    for (int i = 0; i < 2; i++) {
        int q = tid + 256 * i;
        int r = q >> 2, cb = (q & 3) * 16;
        *(uint4*)(buf + 2 * TILE_B + r * TSTRIDE + cb) = pbh[i];
        *(uint4*)(buf + 3 * TILE_B + r * TSTRIDE + cb) = pbl[i];
    }
}

__global__ void __launch_bounds__(256, 1)
tc_gemm(const float* __restrict__ A,
        const __nv_bfloat16* __restrict__ bHiT, const __nv_bfloat16* __restrict__ bLoT,
        const float* __restrict__ bias,
        float* __restrict__ Cf,
        __nv_bfloat16* __restrict__ Chi, __nv_bfloat16* __restrict__ Clo,
        float scale)
{
    extern __shared__ char sm[];
    const int tid = threadIdx.x;
    const int wid = tid >> 5, lane = tid & 31;
    const int wm = wid & 1, wn = wid >> 1;
    const int m0 = blockIdx.x * MT;
    const int n0 = blockIdx.y * NT;

    float acc[4][4][4];
    #pragma unroll
    for (int i = 0; i < 4; i++)
        #pragma unroll
        for (int j = 0; j < 4; j++)
            #pragma unroll
            for (int e = 0; e < 4; e++) acc[i][j][e] = 0.f;

    uint4 pa[4], pbh[2], pbl[2];
    ldg_tiles(A, bHiT, bLoT, m0, n0, 0, tid, pa, pbh, pbl);
    sts_tiles(sm, tid, pa, pbh, pbl);
    __syncthreads();

    const int aRow  = wm * 64 + (lane & 15);
    const int aKoff = ((lane >> 4) & 1) * 16;
    const int bRow  = wn * 32 + (lane & 7);
    const int bKoff = ((lane >> 3) & 1) * 16;

    for (int c = 0; c < 16; c++) {
        char* buf = sm + (c & 1) * BUF_B;
        if (c < 15)
            ldg_tiles(A, bHiT, bLoT, m0, n0, (c + 1) * KC, tid, pa, pbh, pbl);

        const uint32_t base = smem_u32(buf);
        #pragma unroll
        for (int ks = 0; ks < 2; ks++) {
            uint32_t bh[4][2], bl[4][2];
            #pragma unroll
            for (int nt = 0; nt < 4; nt++) {
                uint32_t ad = base + 2 * TILE_B + (bRow + nt * 8) * TSTRIDE
                            + ks * 32 + bKoff;
                ldm2(bh[nt], ad);
                ldm2(bl[nt], ad + TILE_B);
            }
            #pragma unroll
            for (int mt = 0; mt < 4; mt++) {
                uint32_t ah[4], al[4];
                uint32_t ad = base + (aRow + mt * 16) * TSTRIDE + ks * 32 + aKoff;
                ldm4(ah, ad);
                ldm4(al, ad + TILE_B);
                #pragma unroll
                for (int nt = 0; nt < 4; nt++) {
                    mma16816(acc[mt][nt], ah, bh[nt]);
                    mma16816(acc[mt][nt], ah, bl[nt]);
                    mma16816(acc[mt][nt], al, bh[nt]);
                }
            }
        }
        if (c < 15)
            sts_tiles(sm + ((c + 1) & 1) * BUF_B, tid, pa, pbh, pbl);
        __syncthreads();
    }

    const int mBase = m0 + wm * 64 + (lane >> 2);
    const int nBase = n0 + wn * 32 + (lane & 3) * 2;
    if (Cf) {
        #pragma unroll
        for (int nt = 0; nt < 4; nt++) {
            int gn = nBase + nt * 8;
            float b0 = bias[gn], b1 = bias[gn + 1];
            #pragma unroll
            for (int mt = 0; mt < 4; mt++) {
                int gm = mBase + mt * 16;
                *(float2*)&Cf[(size_t)gm * DD + gn] =
                    make_float2(acc[mt][nt][0] + b0, acc[mt][nt][1] + b1);
                *(float2*)&Cf[(size_t)(gm + 8) * DD + gn] =
                    make_float2(acc[mt][nt][2] + b0, acc[mt][nt][3] + b1);
            }
        }
    } else {
        #pragma unroll
        for (int nt = 0; nt < 4; nt++) {
            int gn = nBase + nt * 8;
            float b0 = bias[gn], b1 = bias[gn + 1];
            #pragma unroll
            for (int mt = 0; mt < 4; mt++) {
                int gm = mBase + mt * 16;
                #pragma unroll
                for (int rr = 0; rr < 2; rr++) {
                    float v0 = (acc[mt][nt][rr * 2 + 0] + b0) * scale;
                    float v1 = (acc[mt][nt][rr * 2 + 1] + b1) * scale;
                    __nv_bfloat16 h0 = __float2bfloat16(v0);
                    __nv_bfloat16 h1 = __float2bfloat16(v1);
                    size_t off = (size_t)(gm + rr * 8) * DD + gn;
                    *(uint32_t*)&Chi[off] = pkbf(h0, h1);
                    *(uint32_t*)&Clo[off] = pkbf(
                        __float2bfloat16(v0 - __bfloat162float(h0)),
                        __float2bfloat16(v1 - __bfloat162float(h1)));
                }
            }
        }
    }
}

// ---------------------------------------------------------------------------
// Tensor-core sliding-window flash attention.
// Grid (S/64, H, B), 128 threads (4 warps x 16 query rows).
// Q pre-scaled bf16 hi/lo from GEMM epilogue. K non-trans ldmatrix,
// V trans ldmatrix, P split in-register. 3-pass bf16 everywhere.
// All processed key tiles are fully in [0,S) (64-aligned band) -> band mask only.
// ---------------------------------------------------------------------------
#define AT_STRIDE 144
#define PLANE (64 * AT_STRIDE)            // 9216
#define KV_OFF (2 * PLANE)                // Q hi/lo first
#define KV_BUF (4 * PLANE)                // Khi,Klo,Vhi,Vlo
#define ATTN_SMEM (KV_OFF + 2 * KV_BUF)   // 92160 bytes

__device__ __forceinline__ void stage_kv(uint32_t sbase, size_t rowb, int h,
                                         int n0, int tid)
{
    const int c = (tid & 7) * 16;
    #pragma unroll
    for (int i = 0; i < 16; i++) {
        const __nv_bfloat16* src = (i < 4) ? g_kHi : (i < 8) ? g_kLo
                                 : (i < 12) ? g_vHi : g_vLo;
        int rr = (tid + 128 * (i & 3)) >> 3;
        const char* g = (const char*)(src + (rowb + n0 + rr) * DD + h * HD) + c;
        cpa16(sbase + (i >> 2) * PLANE + rr * AT_STRIDE + c, g);
    }
}

__global__ void __launch_bounds__(128, 2) attn_tc()
{
    extern __shared__ char smc[];
    const uint32_t smb = smem_u32(smc);
    const int tid = threadIdx.x, wid = tid >> 5, lane = tid & 31;
    const int b = blockIdx.z, h = blockIdx.y, m0 = blockIdx.x * 64;
    const size_t rowb = (size_t)b * SS;
    const int wq = wid * 16;

    // stage Q hi/lo (group 0, together with first KV tile)
    {
        const int c = (tid & 7) * 16;
        #pragma unroll
        for (int i = 0; i < 8; i++) {
            const __nv_bfloat16* src = (i < 4) ? g_qHi : g_qLo;
            int rr = (tid + 128 * (i & 3)) >> 3;
            const char* g = (const char*)(src + (rowb + m0 + rr) * DD + h * HD) + c;
            cpa16(smb + (i >> 2) * PLANE + rr * AT_STRIDE + c, g);
        }
    }
    int t_lo = (m0 >= 256) ? 0 : (256 - m0) / 64;
    int t_hi = (SS - 64 - m0 + 256) / 64; if (t_hi > 8) t_hi = 8;

    stage_kv(smb + KV_OFF, rowb, h, m0 - 256 + t_lo * 64, tid);
    asm volatile("cp.async.commit_group;" ::: "memory");

    uint32_t qh[4][4], ql[4][4];
    float O[8][4];
    #pragma unroll
    for (int i = 0; i < 8; i++)
        #pragma unroll
        for (int e = 0; e < 4; e++) O[i][e] = 0.f;
    float mi0 = -1e30f, mi1 = -1e30f, li0 = 0.f, li1 = 0.f;

    for (int t = t_lo; t <= t_hi; t++) {
        const uint32_t cbase = smb + KV_OFF + ((t - t_lo) & 1) * KV_BUF;
        if (t < t_hi) {
            stage_kv(smb + KV_OFF + ((t - t_lo + 1) & 1) * KV_BUF,
                     rowb, h, m0 - 256 + (t + 1) * 64, tid);
            asm volatile("cp.async.commit_group;" ::: "memory");
            asm volatile("cp.async.wait_group 1;" ::: "memory");
        } else {
            asm volatile("cp.async.wait_group 0;" ::: "memory");
        }
        __syncthreads();

        if (t == t_lo) {
            #pragma unroll
            for (int ks = 0; ks < 4; ks++) {
                uint32_t a = smb + (wq + (lane & 15)) * AT_STRIDE
                           + ks * 32 + ((lane >> 4) & 1) * 16;
                ldm4(qh[ks], a);
                ldm4(ql[ks], a + PLANE);
            }
        }
        const int n0 = m0 - 256 + t * 64;

        // ---- S = Q K^T (16 x 64 per warp) ----
        float s[8][4];
        #pragma unroll
        for (int nt = 0; nt < 8; nt++) {
            uint32_t kh[8], kl[8];
            #pragma unroll
            for (int kp = 0; kp < 2; kp++) {
                uint32_t a = cbase + (nt * 8 + (lane & 7)) * AT_STRIDE
                           + kp * 64 + (lane >> 3) * 16;
                ldm4(&kh[kp * 4], a);
                ldm4(&kl[kp * 4], a + PLANE);
            }
            #pragma unroll
            for (int e = 0; e < 4; e++) s[nt][e] = 0.f;
            #pragma unroll
            for (int ks = 0; ks < 4; ks++) {
                mma16816(s[nt], qh[ks], &kh[ks * 2]);
                mma16816(s[nt], qh[ks], &kl[ks * 2]);
                mma16816(s[nt], ql[ks], &kh[ks * 2]);
            }
        }

        // ---- band mask + online softmax ----
        const int colb = n0 + (lane & 3) * 2;
        const int row0 = m0 + wq + (lane >> 2);
        #pragma unroll
        for (int nt = 0; nt < 8; nt++) {
            int kg = colb + nt * 8;
            if (abs(kg     - row0)     > HALFW) s[nt][0] = -1e30f;
            if (abs(kg + 1 - row0)     > HALFW) s[nt][1] = -1e30f;
            if (abs(kg     - row0 - 8) > HALFW) s[nt][2] = -1e30f;
            if (abs(kg + 1 - row0 - 8) > HALFW) s[nt][3] = -1e30f;
        }
        float mx0 = -1e30f, mx1 = -1e30f;
        #pragma unroll
        for (int nt = 0; nt < 8; nt++) {
            mx0 = fmaxf(mx0, fmaxf(s[nt][0], s[nt][1]));
            mx1 = fmaxf(mx1, fmaxf(s[nt][2], s[nt][3]));
        }
        mx0 = fmaxf(mx0, __shfl_xor_sync(0xffffffffu, mx0, 1));
        mx0 = fmaxf(mx0, __shfl_xor_sync(0xffffffffu, mx0, 2));
        mx1 = fmaxf(mx1, __shfl_xor_sync(0xffffffffu, mx1, 1));
        mx1 = fmaxf(mx1, __shfl_xor_sync(0xffffffffu, mx1, 2));
        float mn0 = fmaxf(mi0, mx0), mn1 = fmaxf(mi1, mx1);
        float cr0 = __expf(mi0 - mn0), cr1 = __expf(mi1 - mn1);
        mi0 = mn0; mi1 = mn1;
        float rs0 = 0.f, rs1 = 0.f;
        #pragma unroll
        for (int nt = 0; nt < 8; nt++) {
            s[nt][0] = __expf(s[nt][0] - mn0); rs0 += s[nt][0];
            s[nt][1] = __expf(s[nt][1] - mn0); rs0 += s[nt][1];
            s[nt][2] = __expf(s[nt][2] - mn1); rs1 += s[nt][2];
            s[nt][3] = __expf(s[nt][3] - mn1); rs1 += s[nt][3];
        }
        rs0 += __shfl_xor_sync(0xffffffffu, rs0, 1);
        rs0 += __shfl_xor_sync(0xffffffffu, rs0, 2);
        rs1 += __shfl_xor_sync(0xffffffffu, rs1, 1);
        rs1 += __shfl_xor_sync(0xffffffffu, rs1, 2);
        li0 = li0 * cr0 + rs0;
        li1 = li1 * cr1 + rs1;
        #pragma unroll
        for (int nt = 0; nt < 8; nt++) {
            O[nt][0] *= cr0; O[nt][1] *= cr0;
            O[nt][2] *= cr1; O[nt][3] *= cr1;
        }

        // ---- O += P V (P split hi/lo from accum fragments) ----
        #pragma unroll
        for (int ks = 0; ks < 4; ks++) {
            uint32_t aph[4], apl[4];
            #pragma unroll
            for (int j = 0; j < 4; j++) {
                int nt = ks * 2 + (j >> 1);
                int eb = (j & 1) * 2;
                float x0 = s[nt][eb], x1 = s[nt][eb + 1];
                __nv_bfloat16 h0 = __float2bfloat16(x0);
                __nv_bfloat16 h1 = __float2bfloat16(x1);
                aph[j] = pkbf(h0, h1);
                apl[j] = pkbf(__float2bfloat16(x0 - __bfloat162float(h0)),
                              __float2bfloat16(x1 - __bfloat162float(h1)));
            }
            #pragma unroll
            for (int dp = 0; dp < 4; dp++) {
                uint32_t vh[4], vl[4];
                uint32_t a = cbase + 2 * PLANE + (ks * 16 + (lane & 15)) * AT_STRIDE
                           + dp * 32 + ((lane >> 4) & 1) * 16;
                ldm4t(vh, a);
                ldm4t(vl, a + PLANE);
                mma16816(O[2 * dp],     aph, &vh[0]);
                mma16816(O[2 * dp],     aph, &vl[0]);
                mma16816(O[2 * dp],     apl, &vh[0]);
                mma16816(O[2 * dp + 1], aph, &vh[2]);
                mma16816(O[2 * dp + 1], aph, &vl[2]);
                mma16816(O[2 * dp + 1], apl, &vh[2]);
            }
        }
        __syncthreads();
    }

    // ---- normalize + store fp32 ----
    float iv0 = 1.f / li0, iv1 = 1.f / li1;
    const int row0 = m0 + wq + (lane >> 2);
    #pragma unroll
    for (int nt = 0; nt < 8; nt++) {
        int col = h * HD + nt * 8 + (lane & 3) * 2;
        *(float2*)&g_attn[(rowb + row0) * DD + col] =
            make_float2(O[nt][0] * iv0, O[nt][1] * iv0);
        *(float2*)&g_attn[(rowb + row0 + 8) * DD + col] =
            make_float2(O[nt][2] * iv1, O[nt][3] * iv1);
    }
}

// ----------------------------------------------------------------------------
// out = LayerNorm(val + y) * gamma + beta.   One block (256 thr) per row.
// ----------------------------------------------------------------------------
__global__ void add_ln(const float* __restrict__ val, const float* __restrict__ y,
                       const float* __restrict__ gamma, const float* __restrict__ beta,
                       float* __restrict__ out)
{
    const int row = blockIdx.x;
    const int t = threadIdx.x;
    const size_t base = (size_t)row * DD;

    float v0 = val[base + t]       + y[base + t];
    float v1 = val[base + t + 256] + y[base + t + 256];
    float s  = v0 + v1;
    float sq = v0 * v0 + v1 * v1;

    #pragma unroll
    for (int m = 16; m >= 1; m >>= 1) {
        s  += __shfl_xor_sync(0xffffffffu, s,  m);
        sq += __shfl_xor_sync(0xffffffffu, sq, m);
    }
    __shared__ float ssum[8], ssq[8];
    int w = t >> 5, lane = t & 31;
    if (lane == 0) { ssum[w] = s; ssq[w] = sq; }
    __syncthreads();
    float S = 0.f, SQ = 0.f;
    #pragma unroll
    for (int i = 0; i < 8; i++) { S += ssum[i]; SQ += ssq[i]; }

    float mu  = S * (1.0f / DD);
    float var = SQ * (1.0f / DD) - mu * mu;
    float inv = rsqrtf(var + 1e-5f);

    out[base + t]       = (v0 - mu) * inv * gamma[t]       + beta[t];
    out[base + t + 256] = (v1 - mu) * inv * gamma[t + 256] + beta[t + 256];
}

// ----------------------------------------------------------------------------
extern "C" void kernel_launch(void* const* d_in, const int* in_sizes, int n_in,
                              void* d_out, int out_size)
{
    const float* val   = (const float*)d_in[0];
    const float* Wq    = (const float*)d_in[1];
    const float* bq    = (const float*)d_in[2];
    const float* Wk    = (const float*)d_in[3];
    const float* bk    = (const float*)d_in[4];
    const float* Wv    = (const float*)d_in[5];
    const float* bv    = (const float*)d_in[6];
    const float* Wo    = (const float*)d_in[7];
    const float* bo    = (const float*)d_in[8];
    const float* gamma = (const float*)d_in[9];
    const float* beta  = (const float*)d_in[10];
    float* out = (float*)d_out;

    float *pa, *py;
    __nv_bfloat16 *wHiT, *wLoT, *qHi, *qLo, *kHi, *kLo, *vHi, *vLo;
    cudaGetSymbolAddress((void**)&pa, g_attn);
    cudaGetSymbolAddress((void**)&py, g_y);
    cudaGetSymbolAddress((void**)&wHiT, g_wHiT);
    cudaGetSymbolAddress((void**)&wLoT, g_wLoT);
    cudaGetSymbolAddress((void**)&qHi, g_qHi);
    cudaGetSymbolAddress((void**)&qLo, g_qLo);
    cudaGetSymbolAddress((void**)&kHi, g_kHi);
    cudaGetSymbolAddress((void**)&kLo, g_kLo);
    cudaGetSymbolAddress((void**)&vHi, g_vHi);
    cudaGetSymbolAddress((void**)&vLo, g_vLo);

    cudaFuncSetAttribute(tc_gemm,
                         cudaFuncAttributeMaxDynamicSharedMemorySize, GEMM_SMEM);
    cudaFuncSetAttribute(attn_tc,
                         cudaFuncAttributeMaxDynamicSharedMemorySize, ATTN_SMEM);

    convW4<<<dim3(16, 16, 4), dim3(32, 32)>>>(Wq, Wk, Wv, Wo);

    dim3 ggemm(MROWS / MT, DD / NT);   // (64, 4)
    // QKV projections: bf16 split outputs (Q pre-scaled by 1/sqrt(HD)=0.125)
    tc_gemm<<<ggemm, 256, GEMM_SMEM>>>(val, wHiT + 0 * DD * DD, wLoT + 0 * DD * DD,
                                       bq, nullptr, qHi, qLo, 0.125f);
    tc_gemm<<<ggemm, 256, GEMM_SMEM>>>(val, wHiT + 1 * DD * DD, wLoT + 1 * DD * DD,
                                       bk, nullptr, kHi, kLo, 1.0f);
    tc_gemm<<<ggemm, 256, GEMM_SMEM>>>(val, wHiT + 2 * DD * DD, wLoT + 2 * DD * DD,
                                       bv, nullptr, vHi, vLo, 1.0f);

    dim3 gattn(SS / 64, HH, BB);       // (64, 8, 2)
    attn_tc<<<gattn, 128, ATTN_SMEM>>>();

    // O projection: fp32 output
    tc_gemm<<<ggemm, 256, GEMM_SMEM>>>(pa, wHiT + 3 * DD * DD, wLoT + 3 * DD * DD,
                                       bo, py, nullptr, nullptr, 1.0f);

    add_ln<<<MROWS, 256>>>(val, py, gamma, beta, out);
}